// round 7
// baseline (speedup 1.0000x reference)
#include <cuda_runtime.h>
#include <cuda_bf16.h>
#include <math.h>

// Shapes fixed by the problem
#define NN     1024
#define LL     30
#define LP     32      // padded latent (2 zero lanes)
#define GG     10000
#define NBATCH 64
#define NT     128     // threads per block
#define GT     256     // genes per block (2 per thread)
#define CH     32      // cells per chunk staged in shared

// Scratch (allocation-free rule: __device__ globals)
__device__ int g_order[NN];
__device__ int g_bstart[NBATCH + 1];

typedef unsigned long long u64;

// ---- packed f32x2 helpers (sm_103a) ---------------------------------------
#define FMA2(d, a, b, c) \
    asm("fma.rn.f32x2 %0, %1, %2, %3;" : "=l"(d) : "l"(a), "l"(b), "l"(c))
#define PACK2(d, lo, hi) \
    asm("mov.b64 %0, {%1, %2};" : "=l"(d) : "f"(lo), "f"(hi))
#define UNPACK2(lo, hi, s) \
    asm("mov.b64 {%0, %1}, %2;" : "=f"(lo), "=f"(hi) : "l"(s))

__device__ __forceinline__ float softplus_fast(float x) {
    return fmaxf(x, 0.f) + __logf(1.f + __expf(-fabsf(x)));
}

// ---------------------------------------------------------------------------
// Kernel 1: fused prep. Blocks 0..39: inverse dispersion tail exp(px_r).
// Block 40: counting-sort of cells by batch (256 threads x 4 cells).
// ---------------------------------------------------------------------------
__global__ void prep_kernel(const int* __restrict__ bc,
                            const float* __restrict__ px_r,
                            float* __restrict__ out) {
    if (blockIdx.x < 40) {
        int i = blockIdx.x * 256 + threadIdx.x;
        if (i < GG) out[(size_t)NN * GG + i] = __expf(px_r[i]);
        return;
    }
    __shared__ int cnt[NBATCH];
    __shared__ int start[NBATCH + 1];
    __shared__ int cur[NBATCH];
    int t = threadIdx.x;
    if (t < NBATCH) cnt[t] = 0;
    __syncthreads();
    int myb[4];
#pragma unroll
    for (int q = 0; q < 4; q++) {
        myb[q] = bc[t + q * 256];
        atomicAdd(&cnt[myb[q]], 1);
    }
    __syncthreads();
    if (t == 0) {
        int s = 0;
        for (int i = 0; i < NBATCH; i++) { start[i] = s; s += cnt[i]; }
        start[NBATCH] = s;
    }
    __syncthreads();
    if (t < NBATCH) cur[t] = start[t];
    __syncthreads();
#pragma unroll
    for (int q = 0; q < 4; q++) {
        int p = atomicAdd(&cur[myb[q]], 1);
        g_order[p] = t + q * 256;
    }
    if (t <= NBATCH) g_bstart[t] = start[t];
}

// ---------------------------------------------------------------------------
// Kernel 2: main decoder. Grid = (ceil(G/GT), NB), 128 threads x 2 genes.
// A tile staged in shared (DRAM-read exactly once), W+A folded into packed
// f32x2 registers for BOTH genes, cells streamed through shared. Per cell:
// 8 LDS.128 (loaded straight into u64 pair registers) feed 32 FMA2 across
// 4 independent accumulator chains.
// ---------------------------------------------------------------------------
__global__ __launch_bounds__(NT)
void decoder_kernel(const float* __restrict__ z,
                    const float* __restrict__ sf,
                    const float* __restrict__ W,
                    const float* __restrict__ A,
                    const float* __restrict__ bemb,
                    float* __restrict__ out) {
    __shared__ __align__(16) float Ash[GT * LL];   // 30720 B
    __shared__ __align__(16) float zsh[CH * LP];   // 4096 B
    __shared__ float sfsh[CH];
    __shared__ int   nsh[CH];

    const int tid = threadIdx.x;
    const int g0  = blockIdx.x * GT;
    const int b   = blockIdx.y;
    const int gt  = min(GT, GG - g0);

    const int gA = g0 + tid;
    const int gB = gA + NT;
    const bool actA = (tid < gt);
    const bool actB = (tid + NT < gt);

    // Stage A tile: contiguous gt*30 floats, float4 coalesced
    {
        const float4* Abase = (const float4*)(A + ((size_t)b * GG + g0) * LL);
        float4* As4 = (float4*)Ash;
        const int n4 = (gt * LL) >> 2;   // gt even -> divisible by 4 (well, /2; gt*30/4 integer since gt even)
        for (int i = tid; i < n4; i += NT) As4[i] = Abase[i];
    }
    __syncthreads();

    // Fold C[l] = W[l,g] + A[b,g,l] for both genes into packed f32x2 regs.
    // W is 1.2MB and reused by all 64 batches -> L2-resident.
    u64 C2a[LP / 2], C2b[LP / 2];
    float bbA = 0.f, bbB = 0.f;
#pragma unroll
    for (int q = 0; q < LP / 2; q++) { C2a[q] = 0ULL; C2b[q] = 0ULL; }
    if (actA) {
        float Cr[LP];
#pragma unroll
        for (int l = 0; l < LL; l++) Cr[l] = Ash[tid * LL + l] + W[l * GG + gA];
        Cr[30] = 0.f; Cr[31] = 0.f;
#pragma unroll
        for (int q = 0; q < LP / 2; q++) PACK2(C2a[q], Cr[2 * q], Cr[2 * q + 1]);
        bbA = bemb[(size_t)b * GG + gA];
    }
    if (actB) {
        float Cr[LP];
#pragma unroll
        for (int l = 0; l < LL; l++) Cr[l] = Ash[(tid + NT) * LL + l] + W[l * GG + gB];
        Cr[30] = 0.f; Cr[31] = 0.f;
#pragma unroll
        for (int q = 0; q < LP / 2; q++) PACK2(C2b[q], Cr[2 * q], Cr[2 * q + 1]);
        bbB = bemb[(size_t)b * GG + gB];
    }

    const int s = g_bstart[b];
    const int e = g_bstart[b + 1];

    for (int c0 = s; c0 < e; c0 += CH) {
        const int nch = min(CH, e - c0);
        __syncthreads();   // zsh reuse safety
        if (tid < nch) {
            int n = g_order[c0 + tid];
            nsh[tid]  = n;
            sfsh[tid] = sf[n];
        }
        __syncthreads();   // nsh visible for staging
        // stage z rows, padded stride LP=32, pad lanes zeroed
        for (int i = tid; i < nch * LP; i += NT) {
            int j = i >> 5, l = i & 31;
            zsh[i] = (l < LL) ? z[nsh[j] * LL + l] : 0.f;
        }
        __syncthreads();

        for (int j = 0; j < nch; j++) {
            // 8 LDS.128 directly into u64 pair registers (no PACK movs):
            // little-endian float pair in memory == f32x2 lane order.
            const ulonglong2* zp = (const ulonglong2*)(zsh + j * LP);
            u64 zq[LP / 2];
#pragma unroll
            for (int q = 0; q < 8; q++) {
                ulonglong2 v = zp[q];
                zq[2 * q] = v.x; zq[2 * q + 1] = v.y;
            }
            u64 aA0 = 0ULL, aA1 = 0ULL, aB0 = 0ULL, aB1 = 0ULL;
#pragma unroll
            for (int q = 0; q < 8; q++) {
                FMA2(aA0, C2a[2 * q],     zq[2 * q],     aA0);
                FMA2(aA1, C2a[2 * q + 1], zq[2 * q + 1], aA1);
                FMA2(aB0, C2b[2 * q],     zq[2 * q],     aB0);
                FMA2(aB1, C2b[2 * q + 1], zq[2 * q + 1], aB1);
            }
            const float sfj = sfsh[j];
            const size_t rowbase = (size_t)nsh[j] * GG;
            if (actA) {
                float x0, x1, y0, y1;
                UNPACK2(x0, x1, aA0);
                UNPACK2(y0, y1, aA1);
                float acc = ((x0 + x1) + (y0 + y1)) + bbA;
                out[rowbase + gA] = softplus_fast(acc) * sfj;
            }
            if (actB) {
                float x0, x1, y0, y1;
                UNPACK2(x0, x1, aB0);
                UNPACK2(y0, y1, aB1);
                float acc = ((x0 + x1) + (y0 + y1)) + bbB;
                out[rowbase + gB] = softplus_fast(acc) * sfj;
            }
        }
    }
}

// ---------------------------------------------------------------------------
// Launch. Inputs per metadata order:
//   0: z [N,L] f32        1: batch_covariate [N] i32   2: size_factor [N,1] f32
//   3: W_amat [L,G] f32   4: A_emb [NB,G,L] f32        5: b_emb [NB,G] f32
//   6: px_r [G] f32
// Output: mean [N,G] f32 followed by inverse_dispersion [G] f32.
// ---------------------------------------------------------------------------
extern "C" void kernel_launch(void* const* d_in, const int* in_sizes, int n_in,
                              void* d_out, int out_size) {
    const float* z    = (const float*)d_in[0];
    const int*   bc   = (const int*)  d_in[1];
    const float* sf   = (const float*)d_in[2];
    const float* W    = (const float*)d_in[3];
    const float* A    = (const float*)d_in[4];
    const float* bemb = (const float*)d_in[5];
    const float* pxr  = (const float*)d_in[6];
    float* out = (float*)d_out;

    prep_kernel<<<41, 256>>>(bc, pxr, out);

    dim3 grid((GG + GT - 1) / GT, NBATCH);
    decoder_kernel<<<grid, NT>>>(z, sf, W, A, bemb, out);
}

// round 8
// speedup vs baseline: 1.4489x; 1.4489x over previous
#include <cuda_runtime.h>
#include <cuda_bf16.h>
#include <math.h>

// Shapes fixed by the problem
#define NN     1024
#define LL     30
#define LP     32      // padded latent (2 zero lanes)
#define GG     10000
#define NBATCH 64
#define NT     256     // threads per block = genes per block
#define GT     256
#define CH     32      // cells per chunk staged in shared

typedef unsigned long long u64;

// ---- packed f32x2 helpers (sm_103a) ---------------------------------------
#define FMA2(d, a, b, c) \
    asm("fma.rn.f32x2 %0, %1, %2, %3;" : "=l"(d) : "l"(a), "l"(b), "l"(c))
#define ADD2(d, a, b) \
    asm("add.rn.f32x2 %0, %1, %2;" : "=l"(d) : "l"(a), "l"(b))
#define PACK2(d, lo, hi) \
    asm("mov.b64 %0, {%1, %2};" : "=l"(d) : "f"(lo), "f"(hi))
#define UNPACK2(lo, hi, s) \
    asm("mov.b64 {%0, %1}, %2;" : "=f"(lo), "=f"(hi) : "l"(s))

__device__ __forceinline__ float softplus_fast(float x) {
    return fmaxf(x, 0.f) + __logf(1.f + __expf(-fabsf(x)));
}

// ---------------------------------------------------------------------------
// Single fused kernel. Grid = (ceil(G/256), NB). Block (gx, b):
//   - builds the cell list of batch b in shared (bc is 4KB, L2-resident)
//   - loads its A rows DIRECTLY to packed registers (15 LDG.64/thread; each
//     A byte is read by exactly one thread -> same DRAM traffic as staging,
//     none of the smem-crossbar cost)
//   - folds W (coalesced, L2-resident) into C2 packed f32x2 registers
//   - streams cells through a padded shared z buffer: per cell 8 LDS.128
//     (broadcast) + 16 FMA2 on 2 chains, softplus, coalesced STG
//   - b==0 blocks additionally emit the exp(px_r) tail for their gene tile
// ---------------------------------------------------------------------------
__global__ __launch_bounds__(NT, 3)
void decoder_kernel(const float* __restrict__ z,
                    const int*   __restrict__ bc,
                    const float* __restrict__ sf,
                    const float* __restrict__ W,
                    const float* __restrict__ A,
                    const float* __restrict__ bemb,
                    const float* __restrict__ px_r,
                    float* __restrict__ out) {
    __shared__ __align__(16) float zsh[CH * LP];   // 4096 B
    __shared__ float sfsh[CH];
    __shared__ int   lsh[NN];                      // cell ids of this batch (worst case all)
    __shared__ int   cnt;

    const int tid = threadIdx.x;
    const int g0  = blockIdx.x * GT;
    const int b   = blockIdx.y;
    const int gt  = min(GT, GG - g0);
    const int g   = g0 + tid;
    const bool act = (tid < gt);

    if (tid == 0) cnt = 0;

    // exp(px_r) tail, done by the b==0 plane (same gene tiling)
    if (b == 0 && act) out[(size_t)NN * GG + g] = __expf(px_r[g]);

    __syncthreads();

    // Build this batch's cell list (order irrelevant: each cell owns its row)
    for (int i = tid; i < NN; i += NT) {
        if (bc[i] == b) { int p = atomicAdd(&cnt, 1); lsh[p] = i; }
    }

    // Fold C[l] = A[b,g,l] + W[l,g] into 16 packed f32x2 regs while the
    // list builds. A row is 120B, 8B-aligned -> 15 LDG.64 straight to u64.
    u64 C2[LP / 2];
    float bb = 0.f;
    if (act) {
        const u64* Arow = (const u64*)(A + ((size_t)b * GG + g) * LL);
        u64 a2[15];
#pragma unroll
        for (int q = 0; q < 15; q++) a2[q] = Arow[q];           // MLP=15
        float wr[LL];
#pragma unroll
        for (int l = 0; l < LL; l++) wr[l] = W[l * GG + g];     // coalesced, L2-hit
#pragma unroll
        for (int q = 0; q < 15; q++) {
            u64 w2;
            PACK2(w2, wr[2 * q], wr[2 * q + 1]);
            ADD2(C2[q], a2[q], w2);
        }
        C2[15] = 0ULL;                                          // pad lanes
        bb = bemb[(size_t)b * GG + g];
    } else {
#pragma unroll
        for (int q = 0; q < LP / 2; q++) C2[q] = 0ULL;
    }

    __syncthreads();
    const int e = cnt;

    for (int c0 = 0; c0 < e; c0 += CH) {
        const int nch = min(CH, e - c0);
        __syncthreads();   // zsh reuse safety
        // stage z rows, padded stride LP=32, pad lanes zeroed
        for (int i = tid; i < nch * LP; i += NT) {
            int j = i >> 5, l = i & 31;
            zsh[i] = (l < LL) ? z[lsh[c0 + j] * LL + l] : 0.f;
        }
        if (tid < nch) sfsh[tid] = sf[lsh[c0 + tid]];
        __syncthreads();

        if (act) {
            for (int j = 0; j < nch; j++) {
                const ulonglong2* zp = (const ulonglong2*)(zsh + j * LP);
                u64 a0 = 0ULL, a1 = 0ULL;
#pragma unroll
                for (int h = 0; h < 2; h++) {
                    // 4 LDS.128 batched (broadcast), then 8 FMA2 on 2 chains
                    ulonglong2 v0 = zp[4 * h + 0];
                    ulonglong2 v1 = zp[4 * h + 1];
                    ulonglong2 v2 = zp[4 * h + 2];
                    ulonglong2 v3 = zp[4 * h + 3];
                    FMA2(a0, C2[8 * h + 0], v0.x, a0);
                    FMA2(a1, C2[8 * h + 1], v0.y, a1);
                    FMA2(a0, C2[8 * h + 2], v1.x, a0);
                    FMA2(a1, C2[8 * h + 3], v1.y, a1);
                    FMA2(a0, C2[8 * h + 4], v2.x, a0);
                    FMA2(a1, C2[8 * h + 5], v2.y, a1);
                    FMA2(a0, C2[8 * h + 6], v3.x, a0);
                    FMA2(a1, C2[8 * h + 7], v3.y, a1);
                }
                float x0, x1, y0, y1;
                UNPACK2(x0, x1, a0);
                UNPACK2(y0, y1, a1);
                float acc = ((x0 + x1) + (y0 + y1)) + bb;
                out[(size_t)lsh[c0 + j] * GG + g] = softplus_fast(acc) * sfsh[j];
            }
        }
    }
}

// ---------------------------------------------------------------------------
// Launch. Inputs per metadata order:
//   0: z [N,L] f32        1: batch_covariate [N] i32   2: size_factor [N,1] f32
//   3: W_amat [L,G] f32   4: A_emb [NB,G,L] f32        5: b_emb [NB,G] f32
//   6: px_r [G] f32
// Output: mean [N,G] f32 followed by inverse_dispersion [G] f32.
// ---------------------------------------------------------------------------
extern "C" void kernel_launch(void* const* d_in, const int* in_sizes, int n_in,
                              void* d_out, int out_size) {
    const float* z    = (const float*)d_in[0];
    const int*   bc   = (const int*)  d_in[1];
    const float* sf   = (const float*)d_in[2];
    const float* W    = (const float*)d_in[3];
    const float* A    = (const float*)d_in[4];
    const float* bemb = (const float*)d_in[5];
    const float* pxr  = (const float*)d_in[6];
    float* out = (float*)d_out;

    dim3 grid((GG + GT - 1) / GT, NBATCH);
    decoder_kernel<<<grid, NT>>>(z, bc, sf, W, A, bemb, pxr, out);
}